// round 13
// baseline (speedup 1.0000x reference)
#include <cuda_runtime.h>
#include <cuda_bf16.h>
#include <cuda_pipeline.h>
#include <mma.h>
#include <cstdint>

using namespace nvcuda;

#define NN     50000
#define NPAD   50048    // = 782*64 = 391*128
#define IN_F   256
#define H_F    128
#define OUT_F  64
#define EMAX   800000

// ---------------------------------------------------------------------------
// Static device scratch
// ---------------------------------------------------------------------------
__device__ __align__(32) float g_t[(size_t)NPAD * H_F];          // GEMM outputs (f32)
__device__ __align__(16) __nv_bfloat16 gx_hi[(size_t)NPAD * IN_F];
__device__ __align__(16) __nv_bfloat16 gx_lo[(size_t)NPAD * IN_F];
__device__ __align__(16) __nv_bfloat16 ga_hi[(size_t)NPAD * H_F];
__device__ __align__(16) __nv_bfloat16 ga_lo[(size_t)NPAD * H_F];
__device__ __align__(16) __nv_bfloat16 gw1_hi[IN_F * H_F];
__device__ __align__(16) __nv_bfloat16 gw1_lo[IN_F * H_F];
__device__ __align__(16) __nv_bfloat16 gw2_hi[H_F * OUT_F];
__device__ __align__(16) __nv_bfloat16 gw2_lo[H_F * OUT_F];
__device__ float g_dinv[NN];
__device__ int   g_cnt[NN];      // invariant: all-zero at entry of every call
__device__ int   g_off[NN + 1];
__device__ int   g_col[EMAX];
__device__ int   g_bsum[256];
__device__ int   g_is64;

__device__ __forceinline__ void split_bf16(float v, __nv_bfloat16& h, __nv_bfloat16& l) {
    h = __float2bfloat16_rn(v);
    l = __float2bfloat16_rn(v - __bfloat162float(h));
}

// ---------------------------------------------------------------------------
// Input pre-split: x -> gx_hi/gx_lo (pad rows zeroed); W1,W2 -> gw*
// ---------------------------------------------------------------------------
__global__ void xsplit_kernel(const float* __restrict__ x) {
    size_t i = (size_t)blockIdx.x * blockDim.x + threadIdx.x;      // quad index
    if (i >= (size_t)NPAD * (IN_F / 4)) return;
    size_t row = i / (IN_F / 4);
    float4 v = (row < NN) ? reinterpret_cast<const float4*>(x)[i]
                          : make_float4(0.f, 0.f, 0.f, 0.f);
    __nv_bfloat16 h0, l0, h1, l1, h2, l2, h3, l3;
    split_bf16(v.x, h0, l0); split_bf16(v.y, h1, l1);
    split_bf16(v.z, h2, l2); split_bf16(v.w, h3, l3);
    __nv_bfloat162* ph = reinterpret_cast<__nv_bfloat162*>(gx_hi) + 2 * i;
    __nv_bfloat162* pl = reinterpret_cast<__nv_bfloat162*>(gx_lo) + 2 * i;
    ph[0] = __nv_bfloat162(h0, h1); ph[1] = __nv_bfloat162(h2, h3);
    pl[0] = __nv_bfloat162(l0, l1); pl[1] = __nv_bfloat162(l2, l3);
}

__global__ void wsplit_kernel(const float* __restrict__ W1, const float* __restrict__ W2) {
    int i = blockIdx.x * blockDim.x + threadIdx.x;                 // quad index
    const int Q1 = IN_F * H_F / 4;
    const int Q2 = H_F * OUT_F / 4;
    if (i >= Q1 + Q2) return;
    const float4 v = (i < Q1) ? reinterpret_cast<const float4*>(W1)[i]
                              : reinterpret_cast<const float4*>(W2)[i - Q1];
    __nv_bfloat16 h0, l0, h1, l1, h2, l2, h3, l3;
    split_bf16(v.x, h0, l0); split_bf16(v.y, h1, l1);
    split_bf16(v.z, h2, l2); split_bf16(v.w, h3, l3);
    __nv_bfloat162* ph;
    __nv_bfloat162* pl;
    if (i < Q1) {
        ph = reinterpret_cast<__nv_bfloat162*>(gw1_hi) + 2 * i;
        pl = reinterpret_cast<__nv_bfloat162*>(gw1_lo) + 2 * i;
    } else {
        ph = reinterpret_cast<__nv_bfloat162*>(gw2_hi) + 2 * (i - Q1);
        pl = reinterpret_cast<__nv_bfloat162*>(gw2_lo) + 2 * (i - Q1);
    }
    ph[0] = __nv_bfloat162(h0, h1); ph[1] = __nv_bfloat162(h2, h3);
    pl[0] = __nv_bfloat162(l0, l1); pl[1] = __nv_bfloat162(l2, l3);
}

// ---------------------------------------------------------------------------
// Edge width autodetect
// ---------------------------------------------------------------------------
__global__ void detect_kernel(const int* __restrict__ ei32) {
    if (threadIdx.x == 0 && blockIdx.x == 0) {
        int allzero = 1;
        for (int i = 0; i < 64; i++)
            if (ei32[2 * i + 1] != 0) { allzero = 0; break; }
        g_is64 = allzero;
    }
}
__device__ __forceinline__ int edge_src(const int* ei, int E, int e) {
    return g_is64 ? ei[2 * (size_t)e] : ei[(size_t)e];
}
__device__ __forceinline__ int edge_dst(const int* ei, int E, int e) {
    return g_is64 ? ei[2 * ((size_t)E + e)] : ei[(size_t)E + e];
}

// ---------------------------------------------------------------------------
// CSR build. g_cnt is all-zero on entry (restored by scatter's decrement).
// ---------------------------------------------------------------------------
__global__ void hist_kernel(const int* __restrict__ ei, int E) {
    int e = blockIdx.x * blockDim.x + threadIdx.x;
    if (e >= E) return;
    int d = edge_dst(ei, E, e);
    if ((unsigned)d < (unsigned)NN) atomicAdd(&g_cnt[d], 1);
}
__global__ void scan_local_kernel(int n) {
    __shared__ int sh[256];
    const int tid = threadIdx.x;
    const int i = blockIdx.x * 256 + tid;
    int v = (i < n) ? g_cnt[i] : 0;
    sh[tid] = v;
    __syncthreads();
#pragma unroll
    for (int off = 1; off < 256; off <<= 1) {
        int u = (tid >= off) ? sh[tid - off] : 0;
        __syncthreads();
        sh[tid] += u;
        __syncthreads();
    }
    if (i < n) g_off[i] = sh[tid] - v;
    if (tid == 255) g_bsum[blockIdx.x] = sh[255];
}
__global__ void scan_bsum_kernel(int nb) {
    __shared__ int sh[256];
    const int tid = threadIdx.x;
    int v = (tid < nb) ? g_bsum[tid] : 0;
    sh[tid] = v;
    __syncthreads();
#pragma unroll
    for (int off = 1; off < 256; off <<= 1) {
        int u = (tid >= off) ? sh[tid - off] : 0;
        __syncthreads();
        sh[tid] += u;
        __syncthreads();
    }
    if (tid < nb) g_bsum[tid] = sh[tid] - v;
}
__global__ void scan_apply_kernel(int n) {
    int i = blockIdx.x * 256 + threadIdx.x;
    if (i >= n) return;
    int base = g_bsum[blockIdx.x];
    int c = g_cnt[i];                 // NOT reset here; scatter decrements to 0
    int o = g_off[i] + base;
    g_off[i] = o;
    g_dinv[i] = rsqrtf((float)(c + 1));
    if (i == n - 1) g_off[n] = o + c;
}
__global__ void scatter_kernel(const int* __restrict__ ei, int E) {
    int e = blockIdx.x * blockDim.x + threadIdx.x;
    if (e >= E) return;
    int s = edge_src(ei, E, e);
    int d = edge_dst(ei, E, e);
    if ((unsigned)d >= (unsigned)NN) return;
    int r = atomicAdd(&g_cnt[d], -1);            // restores cnt to 0 for next call
    if ((unsigned)s < (unsigned)NN) g_col[g_off[d] + r - 1] = s;
}

// ---------------------------------------------------------------------------
// Aggregation (gather, warp per dst).
// ---------------------------------------------------------------------------
__global__ void agg1_kernel(const float* __restrict__ b1, int n) {
    int gw   = (blockIdx.x * blockDim.x + threadIdx.x) >> 5;
    int lane = threadIdx.x & 31;
    if (gw >= n) return;
    const float4* __restrict__ trow = reinterpret_cast<const float4*>(g_t);

    float wd = g_dinv[gw];
    float ws = wd * wd;
    float4 v = trow[(size_t)gw * 32 + lane];  // self-loop
    float4 acc = make_float4(v.x * ws, v.y * ws, v.z * ws, v.w * ws);

    int beg = g_off[gw], end = g_off[gw + 1];
    for (int e = beg; e < end; e++) {
        int s = g_col[e];
        float w = g_dinv[s] * wd;
        float4 u = trow[(size_t)s * 32 + lane];
        acc.x = fmaf(u.x, w, acc.x);
        acc.y = fmaf(u.y, w, acc.y);
        acc.z = fmaf(u.z, w, acc.z);
        acc.w = fmaf(u.w, w, acc.w);
    }
    float4 bb = reinterpret_cast<const float4*>(b1)[lane];
    acc.x = fmaxf(acc.x + bb.x, 0.f);
    acc.y = fmaxf(acc.y + bb.y, 0.f);
    acc.z = fmaxf(acc.z + bb.z, 0.f);
    acc.w = fmaxf(acc.w + bb.w, 0.f);

    __nv_bfloat16 h0, l0, h1, l1, h2, l2, h3, l3;
    split_bf16(acc.x, h0, l0); split_bf16(acc.y, h1, l1);
    split_bf16(acc.z, h2, l2); split_bf16(acc.w, h3, l3);
    size_t o = (size_t)gw * (H_F / 2) + lane * 2;   // bf16x2 index
    reinterpret_cast<__nv_bfloat162*>(ga_hi)[o]     = __nv_bfloat162(h0, h1);
    reinterpret_cast<__nv_bfloat162*>(ga_hi)[o + 1] = __nv_bfloat162(h2, h3);
    reinterpret_cast<__nv_bfloat162*>(ga_lo)[o]     = __nv_bfloat162(l0, l1);
    reinterpret_cast<__nv_bfloat162*>(ga_lo)[o + 1] = __nv_bfloat162(l2, l3);
}

__global__ void agg2_kernel(const float* __restrict__ b2, float* __restrict__ out, int n) {
    int gw   = (blockIdx.x * blockDim.x + threadIdx.x) >> 5;
    int lane = threadIdx.x & 31;
    if (gw >= n) return;
    const float2* __restrict__ trow = reinterpret_cast<const float2*>(g_t);

    float wd = g_dinv[gw];
    float ws = wd * wd;
    float2 v = trow[(size_t)gw * 32 + lane];
    float2 acc = make_float2(v.x * ws, v.y * ws);

    int beg = g_off[gw], end = g_off[gw + 1];
    for (int e = beg; e < end; e++) {
        int s = g_col[e];
        float w = g_dinv[s] * wd;
        float2 u = trow[(size_t)s * 32 + lane];
        acc.x = fmaf(u.x, w, acc.x);
        acc.y = fmaf(u.y, w, acc.y);
    }
    float2 bb = reinterpret_cast<const float2*>(b2)[lane];
    acc.x += bb.x;
    acc.y += bb.y;
    reinterpret_cast<float2*>(out)[(size_t)gw * 32 + lane] = acc;
}

// ---------------------------------------------------------------------------
// 2-stage cp.async bf16 GEMM (hi/lo compensated, 3 MMAs, lo*lo dropped).
// BKP=40 (80B rows, conflict-free) + regs<=64 -> 4 blocks/SM for GEMM1.
// ---------------------------------------------------------------------------
template<int BM, int BN, int BK, int WM, int WN, int K, int N>
__global__ void __launch_bounds__(256, 4)
gemm_pipe_kernel(int Asel) {
    constexpr int BKP = 40;                     // A row stride (80B, 16B-aligned)
    constexpr int BNP = (BN == 128) ? 136 : 80; // B row stride
    constexpr int WARPS_N = BN / WN;
    constexpr int AM = WM / 16;
    constexpr int AN = WN / 16;
    constexpr int KK = BK / 16;
    constexpr int T = K / BK;
    constexpr int SA = BM * BKP * 2;            // bytes per A array per stage
    constexpr int SB = BK * BNP * 2;
    constexpr int STAGE = 2 * SA + 2 * SB;
    static_assert((BM / WM) * (BN / WN) == 8, "8 warps");

    const __nv_bfloat16* __restrict__ Ahi = Asel ? ga_hi : gx_hi;
    const __nv_bfloat16* __restrict__ Alo = Asel ? ga_lo : gx_lo;
    const __nv_bfloat16* __restrict__ Bhi = Asel ? gw2_hi : gw1_hi;
    const __nv_bfloat16* __restrict__ Blo = Asel ? gw2_lo : gw1_lo;
    float* __restrict__ C = g_t;

    extern __shared__ __align__(32) char smem_raw[];

    const int tid = threadIdx.x;
    const int wid = tid >> 5;
    const int wm = wid / WARPS_N;
    const int wn = wid % WARPS_N;
    const int row0 = blockIdx.x * BM;

    auto as_hi = [&](int s) { return reinterpret_cast<__nv_bfloat16*>(smem_raw + s * STAGE); };
    auto as_lo = [&](int s) { return reinterpret_cast<__nv_bfloat16*>(smem_raw + s * STAGE + SA); };
    auto bs_hi = [&](int s) { return reinterpret_cast<__nv_bfloat16*>(smem_raw + s * STAGE + 2 * SA); };
    auto bs_lo = [&](int s) { return reinterpret_cast<__nv_bfloat16*>(smem_raw + s * STAGE + 2 * SA + SB); };

    auto copy_stage = [&](int s, int t) {
        const int kbase = t * BK;
#pragma unroll
        for (int idx = tid; idx < BM * (BK / 8); idx += 256) {
            int r = idx / (BK / 8), q = idx % (BK / 8);
            size_t go = (size_t)(row0 + r) * K + kbase + q * 8;
            int so = r * BKP + q * 8;
            __pipeline_memcpy_async(as_hi(s) + so, Ahi + go, 16);
            __pipeline_memcpy_async(as_lo(s) + so, Alo + go, 16);
        }
#pragma unroll
        for (int idx = tid; idx < BK * (BN / 8); idx += 256) {
            int r = idx / (BN / 8), q = idx % (BN / 8);
            size_t go = (size_t)(kbase + r) * N + q * 8;
            int so = r * BNP + q * 8;
            __pipeline_memcpy_async(bs_hi(s) + so, Bhi + go, 16);
            __pipeline_memcpy_async(bs_lo(s) + so, Blo + go, 16);
        }
    };

    wmma::fragment<wmma::accumulator, 16, 16, 16, float> acc[AM][AN];
#pragma unroll
    for (int m = 0; m < AM; m++)
#pragma unroll
        for (int n = 0; n < AN; n++) wmma::fill_fragment(acc[m][n], 0.f);

    copy_stage(0, 0);
    __pipeline_commit();

    for (int t = 0; t < T; t++) {
        __pipeline_wait_prior(0);
        __syncthreads();
        if (t + 1 < T) {
            copy_stage((t + 1) & 1, t + 1);
            __pipeline_commit();
        }
        const int s = t & 1;
#pragma unroll
        for (int kk = 0; kk < KK; kk++) {
            wmma::fragment<wmma::matrix_a, 16, 16, 16, __nv_bfloat16, wmma::row_major> ahi[AM], alo[AM];
#pragma unroll
            for (int m = 0; m < AM; m++) {
                int o = (wm * WM + m * 16) * BKP + kk * 16;
                wmma::load_matrix_sync(ahi[m], as_hi(s) + o, BKP);
                wmma::load_matrix_sync(alo[m], as_lo(s) + o, BKP);
            }
#pragma unroll
            for (int n = 0; n < AN; n++) {
                wmma::fragment<wmma::matrix_b, 16, 16, 16, __nv_bfloat16, wmma::row_major> bhi, blo;
                int o = (kk * 16) * BNP + wn * WN + n * 16;
                wmma::load_matrix_sync(bhi, bs_hi(s) + o, BNP);
                wmma::load_matrix_sync(blo, bs_lo(s) + o, BNP);
#pragma unroll
                for (int m = 0; m < AM; m++) {
                    wmma::mma_sync(acc[m][n], alo[m], bhi, acc[m][n]);
                    wmma::mma_sync(acc[m][n], ahi[m], blo, acc[m][n]);
                    wmma::mma_sync(acc[m][n], ahi[m], bhi, acc[m][n]);
                }
            }
        }
    }

#pragma unroll
    for (int m = 0; m < AM; m++)
#pragma unroll
        for (int n = 0; n < AN; n++)
            wmma::store_matrix_sync(C + (size_t)(row0 + wm * WM + m * 16) * N + wn * WN + n * 16,
                                    acc[m][n], N, wmma::mem_row_major);
}

// ---------------------------------------------------------------------------
// Launch: fork-join. Chain A (main): xsplit/wsplit + GEMM1.
// Chain B (s2): CSR build. Join before agg1.
// ---------------------------------------------------------------------------
extern "C" void kernel_launch(void* const* d_in, const int* in_sizes, int n_in,
                              void* d_out, int out_size) {
    const float* x   = (const float*)d_in[0];
    const int*   ei  = (const int*)d_in[1];
    const float* W1  = (const float*)d_in[2];
    const float* b1  = (const float*)d_in[3];
    const float* W2  = (const float*)d_in[4];
    const float* b2  = (const float*)d_in[5];
    float*       out = (float*)d_out;

    const int N = in_sizes[0] / IN_F;   // 50000
    const int E = in_sizes[1] / 2;      // 800000
    const int TB = 256;
    const int NB = (N + 255) / 256;

    constexpr int SM1 = 2 * (2 * 64 * 40 * 2 + 2 * 32 * 136 * 2);   // 55296
    constexpr int SM2 = 2 * (2 * 128 * 40 * 2 + 2 * 32 * 80 * 2);   // 61440

    static cudaStream_t s2 = nullptr;
    static cudaEvent_t ev_fork = nullptr, ev_join = nullptr;
    if (s2 == nullptr) {
        cudaStreamCreateWithFlags(&s2, cudaStreamNonBlocking);
        cudaEventCreateWithFlags(&ev_fork, cudaEventDisableTiming);
        cudaEventCreateWithFlags(&ev_join, cudaEventDisableTiming);
        cudaFuncSetAttribute((const void*)gemm_pipe_kernel<64, 128, 32, 32, 32, IN_F, H_F>,
                             cudaFuncAttributeMaxDynamicSharedMemorySize, SM1);
        cudaFuncSetAttribute((const void*)gemm_pipe_kernel<128, 64, 32, 32, 32, H_F, OUT_F>,
                             cudaFuncAttributeMaxDynamicSharedMemorySize, SM2);
    }

    // Fork
    cudaEventRecord(ev_fork, 0);
    cudaStreamWaitEvent(s2, ev_fork, 0);

    // Chain B (s2): CSR build (g_cnt is all-zero by invariant)
    detect_kernel<<<1, 32, 0, s2>>>(ei);
    hist_kernel<<<(E + TB - 1) / TB, TB, 0, s2>>>(ei, E);
    scan_local_kernel<<<NB, 256, 0, s2>>>(N);
    scan_bsum_kernel<<<1, 256, 0, s2>>>(NB);
    scan_apply_kernel<<<NB, 256, 0, s2>>>(N);
    scatter_kernel<<<(E + TB - 1) / TB, TB, 0, s2>>>(ei, E);
    cudaEventRecord(ev_join, s2);

    // Chain A (main): pre-split + GEMM1
    xsplit_kernel<<<(NPAD * (IN_F / 4) + TB - 1) / TB, TB>>>(x);
    wsplit_kernel<<<((IN_F * H_F + H_F * OUT_F) / 4 + TB - 1) / TB, TB>>>(W1, W2);
    gemm_pipe_kernel<64, 128, 32, 32, 32, IN_F, H_F><<<NPAD / 64, 256, SM1>>>(0);

    // Join
    cudaStreamWaitEvent(0, ev_join, 0);

    agg1_kernel<<<(N + 7) / 8, 256>>>(b1, N);
    gemm_pipe_kernel<128, 64, 32, 32, 32, H_F, OUT_F><<<NPAD / 128, 256, SM2>>>(1);
    agg2_kernel<<<(N + 7) / 8, 256>>>(b2, out, N);
}

// round 14
// speedup vs baseline: 1.1728x; 1.1728x over previous
#include <cuda_runtime.h>
#include <cuda_bf16.h>
#include <cuda_pipeline.h>
#include <mma.h>
#include <cstdint>

using namespace nvcuda;

#define NN     50000
#define NPAD   50048    // = 782*64 = 391*128
#define IN_F   256
#define H_F    128
#define OUT_F  64
#define EMAX   800000

// ---------------------------------------------------------------------------
// Static device scratch
// ---------------------------------------------------------------------------
__device__ __align__(32) float g_t[(size_t)NPAD * H_F];          // GEMM outputs (f32)
__device__ __align__(16) __nv_bfloat16 gx_hi[(size_t)NPAD * IN_F];
__device__ __align__(16) __nv_bfloat16 gx_lo[(size_t)NPAD * IN_F];
__device__ __align__(16) __nv_bfloat16 ga_hi[(size_t)NPAD * H_F];
__device__ __align__(16) __nv_bfloat16 ga_lo[(size_t)NPAD * H_F];
__device__ __align__(16) __nv_bfloat16 gw1_hi[IN_F * H_F];
__device__ __align__(16) __nv_bfloat16 gw1_lo[IN_F * H_F];
__device__ __align__(16) __nv_bfloat16 gw2_hi[H_F * OUT_F];
__device__ __align__(16) __nv_bfloat16 gw2_lo[H_F * OUT_F];
__device__ float g_dinv[NN];
__device__ int   g_cnt[NN];      // invariant: all-zero at entry of every call
__device__ int   g_off[NN + 1];
__device__ int   g_col[EMAX];
__device__ int   g_bsum[256];
__device__ int   g_is64;

__device__ __forceinline__ void split_bf16(float v, __nv_bfloat16& h, __nv_bfloat16& l) {
    h = __float2bfloat16_rn(v);
    l = __float2bfloat16_rn(v - __bfloat162float(h));
}

// ---------------------------------------------------------------------------
// Input pre-split: x -> gx_hi/gx_lo (pad rows zeroed); W1,W2 -> gw*
// ---------------------------------------------------------------------------
__global__ void xsplit_kernel(const float* __restrict__ x) {
    size_t i = (size_t)blockIdx.x * blockDim.x + threadIdx.x;      // quad index
    if (i >= (size_t)NPAD * (IN_F / 4)) return;
    size_t row = i / (IN_F / 4);
    float4 v = (row < NN) ? reinterpret_cast<const float4*>(x)[i]
                          : make_float4(0.f, 0.f, 0.f, 0.f);
    __nv_bfloat16 h0, l0, h1, l1, h2, l2, h3, l3;
    split_bf16(v.x, h0, l0); split_bf16(v.y, h1, l1);
    split_bf16(v.z, h2, l2); split_bf16(v.w, h3, l3);
    __nv_bfloat162* ph = reinterpret_cast<__nv_bfloat162*>(gx_hi) + 2 * i;
    __nv_bfloat162* pl = reinterpret_cast<__nv_bfloat162*>(gx_lo) + 2 * i;
    ph[0] = __nv_bfloat162(h0, h1); ph[1] = __nv_bfloat162(h2, h3);
    pl[0] = __nv_bfloat162(l0, l1); pl[1] = __nv_bfloat162(l2, l3);
}

__global__ void wsplit_kernel(const float* __restrict__ W1, const float* __restrict__ W2) {
    int i = blockIdx.x * blockDim.x + threadIdx.x;                 // quad index
    const int Q1 = IN_F * H_F / 4;
    const int Q2 = H_F * OUT_F / 4;
    if (i >= Q1 + Q2) return;
    const float4 v = (i < Q1) ? reinterpret_cast<const float4*>(W1)[i]
                              : reinterpret_cast<const float4*>(W2)[i - Q1];
    __nv_bfloat16 h0, l0, h1, l1, h2, l2, h3, l3;
    split_bf16(v.x, h0, l0); split_bf16(v.y, h1, l1);
    split_bf16(v.z, h2, l2); split_bf16(v.w, h3, l3);
    __nv_bfloat162* ph;
    __nv_bfloat162* pl;
    if (i < Q1) {
        ph = reinterpret_cast<__nv_bfloat162*>(gw1_hi) + 2 * i;
        pl = reinterpret_cast<__nv_bfloat162*>(gw1_lo) + 2 * i;
    } else {
        ph = reinterpret_cast<__nv_bfloat162*>(gw2_hi) + 2 * (i - Q1);
        pl = reinterpret_cast<__nv_bfloat162*>(gw2_lo) + 2 * (i - Q1);
    }
    ph[0] = __nv_bfloat162(h0, h1); ph[1] = __nv_bfloat162(h2, h3);
    pl[0] = __nv_bfloat162(l0, l1); pl[1] = __nv_bfloat162(l2, l3);
}

// ---------------------------------------------------------------------------
// Edge width autodetect
// ---------------------------------------------------------------------------
__global__ void detect_kernel(const int* __restrict__ ei32) {
    if (threadIdx.x == 0 && blockIdx.x == 0) {
        int allzero = 1;
        for (int i = 0; i < 64; i++)
            if (ei32[2 * i + 1] != 0) { allzero = 0; break; }
        g_is64 = allzero;
    }
}
__device__ __forceinline__ int edge_src(const int* ei, int E, int e) {
    return g_is64 ? ei[2 * (size_t)e] : ei[(size_t)e];
}
__device__ __forceinline__ int edge_dst(const int* ei, int E, int e) {
    return g_is64 ? ei[2 * ((size_t)E + e)] : ei[(size_t)E + e];
}

// ---------------------------------------------------------------------------
// CSR build. g_cnt is all-zero on entry (restored by scatter's decrement).
// ---------------------------------------------------------------------------
__global__ void hist_kernel(const int* __restrict__ ei, int E) {
    int e = blockIdx.x * blockDim.x + threadIdx.x;
    if (e >= E) return;
    int d = edge_dst(ei, E, e);
    if ((unsigned)d < (unsigned)NN) atomicAdd(&g_cnt[d], 1);
}
__global__ void scan_local_kernel(int n) {
    __shared__ int sh[256];
    const int tid = threadIdx.x;
    const int i = blockIdx.x * 256 + tid;
    int v = (i < n) ? g_cnt[i] : 0;
    sh[tid] = v;
    __syncthreads();
#pragma unroll
    for (int off = 1; off < 256; off <<= 1) {
        int u = (tid >= off) ? sh[tid - off] : 0;
        __syncthreads();
        sh[tid] += u;
        __syncthreads();
    }
    if (i < n) g_off[i] = sh[tid] - v;
    if (tid == 255) g_bsum[blockIdx.x] = sh[255];
}
__global__ void scan_bsum_kernel(int nb) {
    __shared__ int sh[256];
    const int tid = threadIdx.x;
    int v = (tid < nb) ? g_bsum[tid] : 0;
    sh[tid] = v;
    __syncthreads();
#pragma unroll
    for (int off = 1; off < 256; off <<= 1) {
        int u = (tid >= off) ? sh[tid - off] : 0;
        __syncthreads();
        sh[tid] += u;
        __syncthreads();
    }
    if (tid < nb) g_bsum[tid] = sh[tid] - v;
}
__global__ void scan_apply_kernel(int n) {
    int i = blockIdx.x * 256 + threadIdx.x;
    if (i >= n) return;
    int base = g_bsum[blockIdx.x];
    int c = g_cnt[i];                 // NOT reset here; scatter decrements to 0
    int o = g_off[i] + base;
    g_off[i] = o;
    g_dinv[i] = rsqrtf((float)(c + 1));
    if (i == n - 1) g_off[n] = o + c;
}
__global__ void scatter_kernel(const int* __restrict__ ei, int E) {
    int e = blockIdx.x * blockDim.x + threadIdx.x;
    if (e >= E) return;
    int s = edge_src(ei, E, e);
    int d = edge_dst(ei, E, e);
    if ((unsigned)d >= (unsigned)NN) return;
    int r = atomicAdd(&g_cnt[d], -1);            // restores cnt to 0 for next call
    if ((unsigned)s < (unsigned)NN) g_col[g_off[d] + r - 1] = s;
}

// ---------------------------------------------------------------------------
// Aggregation (gather). agg1: warp per node, edge-unrolled x2 for MLP.
// agg2: half-warp (16 lanes x float4) per node, 2 nodes per warp.
// ---------------------------------------------------------------------------
__global__ void agg1_kernel(const float* __restrict__ b1, int n) {
    int gw   = (blockIdx.x * blockDim.x + threadIdx.x) >> 5;
    int lane = threadIdx.x & 31;
    if (gw >= n) return;
    const float4* __restrict__ trow = reinterpret_cast<const float4*>(g_t);

    float wd = g_dinv[gw];
    float ws = wd * wd;
    float4 v = trow[(size_t)gw * 32 + lane];  // self-loop
    float4 acc = make_float4(v.x * ws, v.y * ws, v.z * ws, v.w * ws);

    int beg = g_off[gw], end = g_off[gw + 1];
    int e = beg;
    for (; e + 1 < end; e += 2) {
        int s0 = g_col[e], s1 = g_col[e + 1];
        float w0 = g_dinv[s0] * wd, w1 = g_dinv[s1] * wd;
        float4 u0 = trow[(size_t)s0 * 32 + lane];
        float4 u1 = trow[(size_t)s1 * 32 + lane];
        acc.x = fmaf(u0.x, w0, acc.x); acc.y = fmaf(u0.y, w0, acc.y);
        acc.z = fmaf(u0.z, w0, acc.z); acc.w = fmaf(u0.w, w0, acc.w);
        acc.x = fmaf(u1.x, w1, acc.x); acc.y = fmaf(u1.y, w1, acc.y);
        acc.z = fmaf(u1.z, w1, acc.z); acc.w = fmaf(u1.w, w1, acc.w);
    }
    if (e < end) {
        int s = g_col[e];
        float w = g_dinv[s] * wd;
        float4 u = trow[(size_t)s * 32 + lane];
        acc.x = fmaf(u.x, w, acc.x); acc.y = fmaf(u.y, w, acc.y);
        acc.z = fmaf(u.z, w, acc.z); acc.w = fmaf(u.w, w, acc.w);
    }
    float4 bb = reinterpret_cast<const float4*>(b1)[lane];
    acc.x = fmaxf(acc.x + bb.x, 0.f);
    acc.y = fmaxf(acc.y + bb.y, 0.f);
    acc.z = fmaxf(acc.z + bb.z, 0.f);
    acc.w = fmaxf(acc.w + bb.w, 0.f);

    __nv_bfloat16 h0, l0, h1, l1, h2, l2, h3, l3;
    split_bf16(acc.x, h0, l0); split_bf16(acc.y, h1, l1);
    split_bf16(acc.z, h2, l2); split_bf16(acc.w, h3, l3);
    size_t o = (size_t)gw * (H_F / 2) + lane * 2;   // bf16x2 index
    reinterpret_cast<__nv_bfloat162*>(ga_hi)[o]     = __nv_bfloat162(h0, h1);
    reinterpret_cast<__nv_bfloat162*>(ga_hi)[o + 1] = __nv_bfloat162(h2, h3);
    reinterpret_cast<__nv_bfloat162*>(ga_lo)[o]     = __nv_bfloat162(l0, l1);
    reinterpret_cast<__nv_bfloat162*>(ga_lo)[o + 1] = __nv_bfloat162(l2, l3);
}

// 64 features: half-warp (16 lanes) x float4 per node, 2 nodes per warp
__global__ void agg2_kernel(const float* __restrict__ b2, float* __restrict__ out, int n) {
    int gh = (blockIdx.x * blockDim.x + threadIdx.x) >> 4;  // half-warp id = node
    int hl = threadIdx.x & 15;
    if (gh >= n) return;
    const float4* __restrict__ trow = reinterpret_cast<const float4*>(g_t);

    float wd = g_dinv[gh];
    float ws = wd * wd;
    float4 v = trow[(size_t)gh * 16 + hl];
    float4 acc = make_float4(v.x * ws, v.y * ws, v.z * ws, v.w * ws);

    int beg = g_off[gh], end = g_off[gh + 1];
    int e = beg;
    for (; e + 1 < end; e += 2) {
        int s0 = g_col[e], s1 = g_col[e + 1];
        float w0 = g_dinv[s0] * wd, w1 = g_dinv[s1] * wd;
        float4 u0 = trow[(size_t)s0 * 16 + hl];
        float4 u1 = trow[(size_t)s1 * 16 + hl];
        acc.x = fmaf(u0.x, w0, acc.x); acc.y = fmaf(u0.y, w0, acc.y);
        acc.z = fmaf(u0.z, w0, acc.z); acc.w = fmaf(u0.w, w0, acc.w);
        acc.x = fmaf(u1.x, w1, acc.x); acc.y = fmaf(u1.y, w1, acc.y);
        acc.z = fmaf(u1.z, w1, acc.z); acc.w = fmaf(u1.w, w1, acc.w);
    }
    if (e < end) {
        int s = g_col[e];
        float w = g_dinv[s] * wd;
        float4 u = trow[(size_t)s * 16 + hl];
        acc.x = fmaf(u.x, w, acc.x); acc.y = fmaf(u.y, w, acc.y);
        acc.z = fmaf(u.z, w, acc.z); acc.w = fmaf(u.w, w, acc.w);
    }
    float4 bb = reinterpret_cast<const float4*>(b2)[hl];
    acc.x += bb.x; acc.y += bb.y; acc.z += bb.z; acc.w += bb.w;
    reinterpret_cast<float4*>(out)[(size_t)gh * 16 + hl] = acc;
}

// ---------------------------------------------------------------------------
// 2-stage cp.async bf16 GEMM (hi/lo compensated, 3 MMAs, lo*lo dropped).
// Round-12 proven config: BKP=48 (96B rows), 59/70 KB smem.
// ---------------------------------------------------------------------------
template<int BM, int BN, int BK, int WM, int WN, int K, int N>
__global__ void __launch_bounds__(256)
gemm_pipe_kernel(int Asel) {
    constexpr int BKP = 48;                     // A row stride (96B, 32B-aligned)
    constexpr int BNP = (BN == 128) ? 136 : 80; // B row stride (32B-aligned)
    constexpr int WARPS_N = BN / WN;
    constexpr int AM = WM / 16;
    constexpr int AN = WN / 16;
    constexpr int KK = BK / 16;
    constexpr int T = K / BK;
    constexpr int SA = BM * BKP * 2;            // bytes per A array per stage
    constexpr int SB = BK * BNP * 2;
    constexpr int STAGE = 2 * SA + 2 * SB;
    static_assert((BM / WM) * (BN / WN) == 8, "8 warps");

    const __nv_bfloat16* __restrict__ Ahi = Asel ? ga_hi : gx_hi;
    const __nv_bfloat16* __restrict__ Alo = Asel ? ga_lo : gx_lo;
    const __nv_bfloat16* __restrict__ Bhi = Asel ? gw2_hi : gw1_hi;
    const __nv_bfloat16* __restrict__ Blo = Asel ? gw2_lo : gw1_lo;
    float* __restrict__ C = g_t;

    extern __shared__ __align__(32) char smem_raw[];

    const int tid = threadIdx.x;
    const int wid = tid >> 5;
    const int wm = wid / WARPS_N;
    const int wn = wid % WARPS_N;
    const int row0 = blockIdx.x * BM;

    auto as_hi = [&](int s) { return reinterpret_cast<__nv_bfloat16*>(smem_raw + s * STAGE); };
    auto as_lo = [&](int s) { return reinterpret_cast<__nv_bfloat16*>(smem_raw + s * STAGE + SA); };
    auto bs_hi = [&](int s) { return reinterpret_cast<__nv_bfloat16*>(smem_raw + s * STAGE + 2 * SA); };
    auto bs_lo = [&](int s) { return reinterpret_cast<__nv_bfloat16*>(smem_raw + s * STAGE + 2 * SA + SB); };

    auto copy_stage = [&](int s, int t) {
        const int kbase = t * BK;
#pragma unroll
        for (int idx = tid; idx < BM * (BK / 8); idx += 256) {
            int r = idx / (BK / 8), q = idx % (BK / 8);
            size_t go = (size_t)(row0 + r) * K + kbase + q * 8;
            int so = r * BKP + q * 8;
            __pipeline_memcpy_async(as_hi(s) + so, Ahi + go, 16);
            __pipeline_memcpy_async(as_lo(s) + so, Alo + go, 16);
        }
#pragma unroll
        for (int idx = tid; idx < BK * (BN / 8); idx += 256) {
            int r = idx / (BN / 8), q = idx % (BN / 8);
            size_t go = (size_t)(kbase + r) * N + q * 8;
            int so = r * BNP + q * 8;
            __pipeline_memcpy_async(bs_hi(s) + so, Bhi + go, 16);
            __pipeline_memcpy_async(bs_lo(s) + so, Blo + go, 16);
        }
    };

    wmma::fragment<wmma::accumulator, 16, 16, 16, float> acc[AM][AN];
#pragma unroll
    for (int m = 0; m < AM; m++)
#pragma unroll
        for (int n = 0; n < AN; n++) wmma::fill_fragment(acc[m][n], 0.f);

    copy_stage(0, 0);
    __pipeline_commit();

    for (int t = 0; t < T; t++) {
        __pipeline_wait_prior(0);
        __syncthreads();
        if (t + 1 < T) {
            copy_stage((t + 1) & 1, t + 1);
            __pipeline_commit();
        }
        const int s = t & 1;
#pragma unroll
        for (int kk = 0; kk < KK; kk++) {
            wmma::fragment<wmma::matrix_a, 16, 16, 16, __nv_bfloat16, wmma::row_major> ahi[AM], alo[AM];
#pragma unroll
            for (int m = 0; m < AM; m++) {
                int o = (wm * WM + m * 16) * BKP + kk * 16;
                wmma::load_matrix_sync(ahi[m], as_hi(s) + o, BKP);
                wmma::load_matrix_sync(alo[m], as_lo(s) + o, BKP);
            }
#pragma unroll
            for (int n = 0; n < AN; n++) {
                wmma::fragment<wmma::matrix_b, 16, 16, 16, __nv_bfloat16, wmma::row_major> bhi, blo;
                int o = (kk * 16) * BNP + wn * WN + n * 16;
                wmma::load_matrix_sync(bhi, bs_hi(s) + o, BNP);
                wmma::load_matrix_sync(blo, bs_lo(s) + o, BNP);
#pragma unroll
                for (int m = 0; m < AM; m++) {
                    wmma::mma_sync(acc[m][n], alo[m], bhi, acc[m][n]);
                    wmma::mma_sync(acc[m][n], ahi[m], blo, acc[m][n]);
                    wmma::mma_sync(acc[m][n], ahi[m], bhi, acc[m][n]);
                }
            }
        }
    }

#pragma unroll
    for (int m = 0; m < AM; m++)
#pragma unroll
        for (int n = 0; n < AN; n++)
            wmma::store_matrix_sync(C + (size_t)(row0 + wm * WM + m * 16) * N + wn * WN + n * 16,
                                    acc[m][n], N, wmma::mem_row_major);
}

// ---------------------------------------------------------------------------
// Launch: fork-join. Chain A (main): xsplit/wsplit + GEMM1.
// Chain B (s2): CSR build. Join before agg1.
// ---------------------------------------------------------------------------
extern "C" void kernel_launch(void* const* d_in, const int* in_sizes, int n_in,
                              void* d_out, int out_size) {
    const float* x   = (const float*)d_in[0];
    const int*   ei  = (const int*)d_in[1];
    const float* W1  = (const float*)d_in[2];
    const float* b1  = (const float*)d_in[3];
    const float* W2  = (const float*)d_in[4];
    const float* b2  = (const float*)d_in[5];
    float*       out = (float*)d_out;

    const int N = in_sizes[0] / IN_F;   // 50000
    const int E = in_sizes[1] / 2;      // 800000
    const int TB = 256;
    const int NB = (N + 255) / 256;

    constexpr int SM1 = 2 * (2 * 64 * 48 * 2 + 2 * 32 * 136 * 2);   // 59392
    constexpr int SM2 = 2 * (2 * 128 * 48 * 2 + 2 * 32 * 80 * 2);   // 69632

    static cudaStream_t s2 = nullptr;
    static cudaEvent_t ev_fork = nullptr, ev_join = nullptr;
    if (s2 == nullptr) {
        cudaStreamCreateWithFlags(&s2, cudaStreamNonBlocking);
        cudaEventCreateWithFlags(&ev_fork, cudaEventDisableTiming);
        cudaEventCreateWithFlags(&ev_join, cudaEventDisableTiming);
        cudaFuncSetAttribute((const void*)gemm_pipe_kernel<64, 128, 32, 32, 32, IN_F, H_F>,
                             cudaFuncAttributeMaxDynamicSharedMemorySize, SM1);
        cudaFuncSetAttribute((const void*)gemm_pipe_kernel<128, 64, 32, 32, 32, H_F, OUT_F>,
                             cudaFuncAttributeMaxDynamicSharedMemorySize, SM2);
    }

    // Fork
    cudaEventRecord(ev_fork, 0);
    cudaStreamWaitEvent(s2, ev_fork, 0);

    // Chain B (s2): CSR build (g_cnt is all-zero by invariant)
    detect_kernel<<<1, 32, 0, s2>>>(ei);
    hist_kernel<<<(E + TB - 1) / TB, TB, 0, s2>>>(ei, E);
    scan_local_kernel<<<NB, 256, 0, s2>>>(N);
    scan_bsum_kernel<<<1, 256, 0, s2>>>(NB);
    scan_apply_kernel<<<NB, 256, 0, s2>>>(N);
    scatter_kernel<<<(E + TB - 1) / TB, TB, 0, s2>>>(ei, E);
    cudaEventRecord(ev_join, s2);

    // Chain A (main): pre-split + GEMM1
    xsplit_kernel<<<(NPAD * (IN_F / 4) + TB - 1) / TB, TB>>>(x);
    wsplit_kernel<<<((IN_F * H_F + H_F * OUT_F) / 4 + TB - 1) / TB, TB>>>(W1, W2);
    gemm_pipe_kernel<64, 128, 32, 32, 32, IN_F, H_F><<<NPAD / 64, 256, SM1>>>(0);

    // Join
    cudaStreamWaitEvent(0, ev_join, 0);

    agg1_kernel<<<(N + 7) / 8, 256>>>(b1, N);
    gemm_pipe_kernel<128, 64, 32, 32, 32, H_F, OUT_F><<<NPAD / 128, 256, SM2>>>(1);
    agg2_kernel<<<(N + 15) / 16, 256>>>(b2, out, N);
}

// round 15
// speedup vs baseline: 1.2599x; 1.0743x over previous
#include <cuda_runtime.h>
#include <cuda_bf16.h>
#include <cuda_pipeline.h>
#include <mma.h>
#include <cstdint>

using namespace nvcuda;

#define NN     50000
#define NPAD   50048    // = 782*64 = 391*128
#define IN_F   256
#define H_F    128
#define OUT_F  64
#define EMAX   800000

// ---------------------------------------------------------------------------
// Static device scratch
// ---------------------------------------------------------------------------
__device__ __align__(32) float g_t[(size_t)NPAD * H_F];          // GEMM outputs (f32)
__device__ __align__(16) __nv_bfloat16 ga_hi[(size_t)NPAD * H_F];
__device__ __align__(16) __nv_bfloat16 ga_lo[(size_t)NPAD * H_F];
__device__ __align__(16) __nv_bfloat16 gw1_hi[IN_F * H_F];
__device__ __align__(16) __nv_bfloat16 gw1_lo[IN_F * H_F];
__device__ __align__(16) __nv_bfloat16 gw2_hi[H_F * OUT_F];
__device__ __align__(16) __nv_bfloat16 gw2_lo[H_F * OUT_F];
__device__ float g_dinv[NN];
__device__ int   g_cnt[NN];      // invariant: all-zero at entry of every call
__device__ int   g_off[NN + 1];
__device__ int   g_col[EMAX];
__device__ int   g_bsum[256];
__device__ int   g_is64;

__device__ __forceinline__ void split_bf16(float v, __nv_bfloat16& h, __nv_bfloat16& l) {
    h = __float2bfloat16_rn(v);
    l = __float2bfloat16_rn(v - __bfloat162float(h));
}

// ---------------------------------------------------------------------------
// Weight pre-split (x split is fused into GEMM1)
// ---------------------------------------------------------------------------
__global__ void wsplit_kernel(const float* __restrict__ W1, const float* __restrict__ W2) {
    int i = blockIdx.x * blockDim.x + threadIdx.x;                 // quad index
    const int Q1 = IN_F * H_F / 4;
    const int Q2 = H_F * OUT_F / 4;
    if (i >= Q1 + Q2) return;
    const float4 v = (i < Q1) ? reinterpret_cast<const float4*>(W1)[i]
                              : reinterpret_cast<const float4*>(W2)[i - Q1];
    __nv_bfloat16 h0, l0, h1, l1, h2, l2, h3, l3;
    split_bf16(v.x, h0, l0); split_bf16(v.y, h1, l1);
    split_bf16(v.z, h2, l2); split_bf16(v.w, h3, l3);
    __nv_bfloat162* ph;
    __nv_bfloat162* pl;
    if (i < Q1) {
        ph = reinterpret_cast<__nv_bfloat162*>(gw1_hi) + 2 * i;
        pl = reinterpret_cast<__nv_bfloat162*>(gw1_lo) + 2 * i;
    } else {
        ph = reinterpret_cast<__nv_bfloat162*>(gw2_hi) + 2 * (i - Q1);
        pl = reinterpret_cast<__nv_bfloat162*>(gw2_lo) + 2 * (i - Q1);
    }
    ph[0] = __nv_bfloat162(h0, h1); ph[1] = __nv_bfloat162(h2, h3);
    pl[0] = __nv_bfloat162(l0, l1); pl[1] = __nv_bfloat162(l2, l3);
}

// ---------------------------------------------------------------------------
// Edge width autodetect
// ---------------------------------------------------------------------------
__global__ void detect_kernel(const int* __restrict__ ei32) {
    if (threadIdx.x == 0 && blockIdx.x == 0) {
        int allzero = 1;
        for (int i = 0; i < 64; i++)
            if (ei32[2 * i + 1] != 0) { allzero = 0; break; }
        g_is64 = allzero;
    }
}
__device__ __forceinline__ int edge_src(const int* ei, int E, int e) {
    return g_is64 ? ei[2 * (size_t)e] : ei[(size_t)e];
}
__device__ __forceinline__ int edge_dst(const int* ei, int E, int e) {
    return g_is64 ? ei[2 * ((size_t)E + e)] : ei[(size_t)E + e];
}

// ---------------------------------------------------------------------------
// CSR build. g_cnt is all-zero on entry (restored by scatter's decrement).
// ---------------------------------------------------------------------------
__global__ void hist_kernel(const int* __restrict__ ei, int E) {
    int e = blockIdx.x * blockDim.x + threadIdx.x;
    if (e >= E) return;
    int d = edge_dst(ei, E, e);
    if ((unsigned)d < (unsigned)NN) atomicAdd(&g_cnt[d], 1);
}
__global__ void scan_local_kernel(int n) {
    __shared__ int sh[256];
    const int tid = threadIdx.x;
    const int i = blockIdx.x * 256 + tid;
    int v = (i < n) ? g_cnt[i] : 0;
    sh[tid] = v;
    __syncthreads();
#pragma unroll
    for (int off = 1; off < 256; off <<= 1) {
        int u = (tid >= off) ? sh[tid - off] : 0;
        __syncthreads();
        sh[tid] += u;
        __syncthreads();
    }
    if (i < n) g_off[i] = sh[tid] - v;
    if (tid == 255) g_bsum[blockIdx.x] = sh[255];
}
__global__ void scan_bsum_kernel(int nb) {
    __shared__ int sh[256];
    const int tid = threadIdx.x;
    int v = (tid < nb) ? g_bsum[tid] : 0;
    sh[tid] = v;
    __syncthreads();
#pragma unroll
    for (int off = 1; off < 256; off <<= 1) {
        int u = (tid >= off) ? sh[tid - off] : 0;
        __syncthreads();
        sh[tid] += u;
        __syncthreads();
    }
    if (tid < nb) g_bsum[tid] = sh[tid] - v;
}
__global__ void scan_apply_kernel(int n) {
    int i = blockIdx.x * 256 + threadIdx.x;
    if (i >= n) return;
    int base = g_bsum[blockIdx.x];
    int c = g_cnt[i];                 // NOT reset here; scatter decrements to 0
    int o = g_off[i] + base;
    g_off[i] = o;
    g_dinv[i] = rsqrtf((float)(c + 1));
    if (i == n - 1) g_off[n] = o + c;
}
__global__ void scatter_kernel(const int* __restrict__ ei, int E) {
    int e = blockIdx.x * blockDim.x + threadIdx.x;
    if (e >= E) return;
    int s = edge_src(ei, E, e);
    int d = edge_dst(ei, E, e);
    if ((unsigned)d >= (unsigned)NN) return;
    int r = atomicAdd(&g_cnt[d], -1);            // restores cnt to 0 for next call
    if ((unsigned)s < (unsigned)NN) g_col[g_off[d] + r - 1] = s;
}

// ---------------------------------------------------------------------------
// Aggregation (gather). agg1: warp per node, edge-unrolled x2.
// agg2: half-warp (16 lanes x float4) per node.
// ---------------------------------------------------------------------------
__global__ void agg1_kernel(const float* __restrict__ b1, int n) {
    int gw   = (blockIdx.x * blockDim.x + threadIdx.x) >> 5;
    int lane = threadIdx.x & 31;
    if (gw >= n) return;
    const float4* __restrict__ trow = reinterpret_cast<const float4*>(g_t);

    float wd = g_dinv[gw];
    float ws = wd * wd;
    float4 v = trow[(size_t)gw * 32 + lane];  // self-loop
    float4 acc = make_float4(v.x * ws, v.y * ws, v.z * ws, v.w * ws);

    int beg = g_off[gw], end = g_off[gw + 1];
    int e = beg;
    for (; e + 1 < end; e += 2) {
        int s0 = g_col[e], s1 = g_col[e + 1];
        float w0 = g_dinv[s0] * wd, w1 = g_dinv[s1] * wd;
        float4 u0 = trow[(size_t)s0 * 32 + lane];
        float4 u1 = trow[(size_t)s1 * 32 + lane];
        acc.x = fmaf(u0.x, w0, acc.x); acc.y = fmaf(u0.y, w0, acc.y);
        acc.z = fmaf(u0.z, w0, acc.z); acc.w = fmaf(u0.w, w0, acc.w);
        acc.x = fmaf(u1.x, w1, acc.x); acc.y = fmaf(u1.y, w1, acc.y);
        acc.z = fmaf(u1.z, w1, acc.z); acc.w = fmaf(u1.w, w1, acc.w);
    }
    if (e < end) {
        int s = g_col[e];
        float w = g_dinv[s] * wd;
        float4 u = trow[(size_t)s * 32 + lane];
        acc.x = fmaf(u.x, w, acc.x); acc.y = fmaf(u.y, w, acc.y);
        acc.z = fmaf(u.z, w, acc.z); acc.w = fmaf(u.w, w, acc.w);
    }
    float4 bb = reinterpret_cast<const float4*>(b1)[lane];
    acc.x = fmaxf(acc.x + bb.x, 0.f);
    acc.y = fmaxf(acc.y + bb.y, 0.f);
    acc.z = fmaxf(acc.z + bb.z, 0.f);
    acc.w = fmaxf(acc.w + bb.w, 0.f);

    __nv_bfloat16 h0, l0, h1, l1, h2, l2, h3, l3;
    split_bf16(acc.x, h0, l0); split_bf16(acc.y, h1, l1);
    split_bf16(acc.z, h2, l2); split_bf16(acc.w, h3, l3);
    size_t o = (size_t)gw * (H_F / 2) + lane * 2;   // bf16x2 index
    reinterpret_cast<__nv_bfloat162*>(ga_hi)[o]     = __nv_bfloat162(h0, h1);
    reinterpret_cast<__nv_bfloat162*>(ga_hi)[o + 1] = __nv_bfloat162(h2, h3);
    reinterpret_cast<__nv_bfloat162*>(ga_lo)[o]     = __nv_bfloat162(l0, l1);
    reinterpret_cast<__nv_bfloat162*>(ga_lo)[o + 1] = __nv_bfloat162(l2, l3);
}

__global__ void agg2_kernel(const float* __restrict__ b2, float* __restrict__ out, int n) {
    int gh = (blockIdx.x * blockDim.x + threadIdx.x) >> 4;  // half-warp id = node
    int hl = threadIdx.x & 15;
    if (gh >= n) return;
    const float4* __restrict__ trow = reinterpret_cast<const float4*>(g_t);

    float wd = g_dinv[gh];
    float ws = wd * wd;
    float4 v = trow[(size_t)gh * 16 + hl];
    float4 acc = make_float4(v.x * ws, v.y * ws, v.z * ws, v.w * ws);

    int beg = g_off[gh], end = g_off[gh + 1];
    int e = beg;
    for (; e + 1 < end; e += 2) {
        int s0 = g_col[e], s1 = g_col[e + 1];
        float w0 = g_dinv[s0] * wd, w1 = g_dinv[s1] * wd;
        float4 u0 = trow[(size_t)s0 * 16 + hl];
        float4 u1 = trow[(size_t)s1 * 16 + hl];
        acc.x = fmaf(u0.x, w0, acc.x); acc.y = fmaf(u0.y, w0, acc.y);
        acc.z = fmaf(u0.z, w0, acc.z); acc.w = fmaf(u0.w, w0, acc.w);
        acc.x = fmaf(u1.x, w1, acc.x); acc.y = fmaf(u1.y, w1, acc.y);
        acc.z = fmaf(u1.z, w1, acc.z); acc.w = fmaf(u1.w, w1, acc.w);
    }
    if (e < end) {
        int s = g_col[e];
        float w = g_dinv[s] * wd;
        float4 u = trow[(size_t)s * 16 + hl];
        acc.x = fmaf(u.x, w, acc.x); acc.y = fmaf(u.y, w, acc.y);
        acc.z = fmaf(u.z, w, acc.z); acc.w = fmaf(u.w, w, acc.w);
    }
    float4 bb = reinterpret_cast<const float4*>(b2)[hl];
    acc.x += bb.x; acc.y += bb.y; acc.z += bb.z; acc.w += bb.w;
    reinterpret_cast<float4*>(out)[(size_t)gh * 16 + hl] = acc;
}

// ---------------------------------------------------------------------------
// GEMM1 with FUSED x split: cp.async raw f32 A tiles, convert to bf16 hi/lo
// in smem (each A element touched by exactly one block: grid is 1-D over M).
// BM=64, BN=128=N, BK=32, WM=32, WN=32, K=256. 256 threads.
// smem: A_f32 2x8KB | A_hi/lo single 2x6KB | B hi/lo 2-stage 34.8KB = 62KB.
// ---------------------------------------------------------------------------
__global__ void __launch_bounds__(256)
gemm1_fused_kernel(const float* __restrict__ x) {
    constexpr int BM = 64, BN = 128, BK = 32, K = IN_F, N = H_F;
    constexpr int BKP = 48;        // A hi/lo row stride (96B)
    constexpr int BNP = 136;       // B row stride (272B)
    constexpr int T = K / BK;      // 8
    constexpr int KK = BK / 16;    // 2
    constexpr int AM = 2, AN = 2, WARPS_N = 4;
    constexpr int AF_STAGE = BM * BK * 4;          // 8192 B
    constexpr int OFF_AF  = 0;                     // 2 stages
    constexpr int OFF_AHI = 2 * AF_STAGE;          // 16384
    constexpr int OFF_ALO = OFF_AHI + BM * BKP * 2;  // +6144
    constexpr int OFF_B   = OFF_ALO + BM * BKP * 2;  // 28672
    constexpr int SB = BK * BNP * 2;               // 8704 per array
    // B stage s: hi at OFF_B + s*2*SB, lo at +SB

    extern __shared__ __align__(32) char smem_raw[];
    float* af = reinterpret_cast<float*>(smem_raw + OFF_AF);
    __nv_bfloat16* ahi_s = reinterpret_cast<__nv_bfloat16*>(smem_raw + OFF_AHI);
    __nv_bfloat16* alo_s = reinterpret_cast<__nv_bfloat16*>(smem_raw + OFF_ALO);

    const int tid = threadIdx.x;
    const int wid = tid >> 5;
    const int wm = wid / WARPS_N;
    const int wn = wid % WARPS_N;
    const int row0 = blockIdx.x * BM;

    auto bs_hi = [&](int s) { return reinterpret_cast<__nv_bfloat16*>(smem_raw + OFF_B + s * 2 * SB); };
    auto bs_lo = [&](int s) { return reinterpret_cast<__nv_bfloat16*>(smem_raw + OFF_B + s * 2 * SB + SB); };

    auto copy_stage = [&](int s, int t) {
        const int kbase = t * BK;
        // A: 512 chunks of 16B (BM rows x BK f32, 8 chunks/row), rows clamped
#pragma unroll
        for (int idx = tid; idx < BM * (BK / 4); idx += 256) {
            int r = idx >> 3, q = idx & 7;
            int gr = row0 + r; if (gr >= NN) gr = NN - 1;   // clamp; zeroed in convert
            __pipeline_memcpy_async(af + s * (AF_STAGE / 4) + idx * 4,
                                    x + (size_t)gr * K + kbase + q * 4, 16);
        }
        // B: BK rows x BN bf16, hi+lo (pre-split weights)
#pragma unroll
        for (int idx = tid; idx < BK * (BN / 8); idx += 256) {
            int r = idx / (BN / 8), q = idx % (BN / 8);
            size_t go = (size_t)(kbase + r) * N + q * 8;
            int so = r * BNP + q * 8;
            __pipeline_memcpy_async(bs_hi(s) + so, gw1_hi + go, 16);
            __pipeline_memcpy_async(bs_lo(s) + so, gw1_lo + go, 16);
        }
    };

    wmma::fragment<wmma::accumulator, 16, 16, 16, float> acc[AM][AN];
#pragma unroll
    for (int m = 0; m < AM; m++)
#pragma unroll
        for (int n = 0; n < AN; n++) wmma::fill_fragment(acc[m][n], 0.f);

    copy_stage(0, 0);
    __pipeline_commit();

    for (int t = 0; t < T; t++) {
        __pipeline_wait_prior(0);
        __syncthreads();                 // copies done; prior MMAs done
        if (t + 1 < T) {
            copy_stage((t + 1) & 1, t + 1);
            __pipeline_commit();
        }
        // Convert A f32 stage -> single hi/lo bf16 buffers
        const int s = t & 1;
#pragma unroll
        for (int idx = tid; idx < BM * (BK / 4); idx += 256) {
            int r = idx >> 3, c = (idx & 7) * 4;
            float4 v = *reinterpret_cast<const float4*>(af + s * (AF_STAGE / 4) + idx * 4);
            if (row0 + r >= NN) v = make_float4(0.f, 0.f, 0.f, 0.f);
            __nv_bfloat16 h0, l0, h1, l1, h2, l2, h3, l3;
            split_bf16(v.x, h0, l0); split_bf16(v.y, h1, l1);
            split_bf16(v.z, h2, l2); split_bf16(v.w, h3, l3);
            int o = r * BKP + c;
            *reinterpret_cast<__nv_bfloat162*>(&ahi_s[o])     = __nv_bfloat162(h0, h1);
            *reinterpret_cast<__nv_bfloat162*>(&ahi_s[o + 2]) = __nv_bfloat162(h2, h3);
            *reinterpret_cast<__nv_bfloat162*>(&alo_s[o])     = __nv_bfloat162(l0, l1);
            *reinterpret_cast<__nv_bfloat162*>(&alo_s[o + 2]) = __nv_bfloat162(l2, l3);
        }
        __syncthreads();
#pragma unroll
        for (int kk = 0; kk < KK; kk++) {
            wmma::fragment<wmma::matrix_a, 16, 16, 16, __nv_bfloat16, wmma::row_major> ahi[AM], alo[AM];
#pragma unroll
            for (int m = 0; m < AM; m++) {
                int o = (wm * 32 + m * 16) * BKP + kk * 16;
                wmma::load_matrix_sync(ahi[m], ahi_s + o, BKP);
                wmma::load_matrix_sync(alo[m], alo_s + o, BKP);
            }
#pragma unroll
            for (int n = 0; n < AN; n++) {
                wmma::fragment<wmma::matrix_b, 16, 16, 16, __nv_bfloat16, wmma::row_major> bhi, blo;
                int o = (kk * 16) * BNP + wn * 32 + n * 16;
                wmma::load_matrix_sync(bhi, bs_hi(s) + o, BNP);
                wmma::load_matrix_sync(blo, bs_lo(s) + o, BNP);
#pragma unroll
                for (int m = 0; m < AM; m++) {
                    wmma::mma_sync(acc[m][n], alo[m], bhi, acc[m][n]);
                    wmma::mma_sync(acc[m][n], ahi[m], blo, acc[m][n]);
                    wmma::mma_sync(acc[m][n], ahi[m], bhi, acc[m][n]);
                }
            }
        }
    }

#pragma unroll
    for (int m = 0; m < AM; m++)
#pragma unroll
        for (int n = 0; n < AN; n++)
            wmma::store_matrix_sync(g_t + (size_t)(row0 + wm * 32 + m * 16) * N + wn * 32 + n * 16,
                                    acc[m][n], N, wmma::mem_row_major);
}

// ---------------------------------------------------------------------------
// GEMM2: pre-split bf16 A (ga), round-12 proven config.
// BM=128, BN=64, BK=32, WM=32, WN=32, K=128, N=64.
// ---------------------------------------------------------------------------
__global__ void __launch_bounds__(256)
gemm2_kernel() {
    constexpr int BM = 128, BN = 64, BK = 32, K = H_F, N = OUT_F;
    constexpr int BKP = 48;
    constexpr int BNP = 80;
    constexpr int WARPS_N = 2;
    constexpr int AM = 2, AN = 2;
    constexpr int KK = 2;
    constexpr int T = K / BK;   // 4
    constexpr int SA = BM * BKP * 2;
    constexpr int SB = BK * BNP * 2;
    constexpr int STAGE = 2 * SA + 2 * SB;

    extern __shared__ __align__(32) char smem_raw[];

    const int tid = threadIdx.x;
    const int wid = tid >> 5;
    const int wm = wid / WARPS_N;
    const int wn = wid % WARPS_N;
    const int row0 = blockIdx.x * BM;

    auto as_hi = [&](int s) { return reinterpret_cast<__nv_bfloat16*>(smem_raw + s * STAGE); };
    auto as_lo = [&](int s) { return reinterpret_cast<__nv_bfloat16*>(smem_raw + s * STAGE + SA); };
    auto bs_hi = [&](int s) { return reinterpret_cast<__nv_bfloat16*>(smem_raw + s * STAGE + 2 * SA); };
    auto bs_lo = [&](int s) { return reinterpret_cast<__nv_bfloat16*>(smem_raw + s * STAGE + 2 * SA + SB); };

    auto copy_stage = [&](int s, int t) {
        const int kbase = t * BK;
#pragma unroll
        for (int idx = tid; idx < BM * (BK / 8); idx += 256) {
            int r = idx / (BK / 8), q = idx % (BK / 8);
            size_t go = (size_t)(row0 + r) * K + kbase + q * 8;
            int so = r * BKP + q * 8;
            __pipeline_memcpy_async(as_hi(s) + so, ga_hi + go, 16);
            __pipeline_memcpy_async(as_lo(s) + so, ga_lo + go, 16);
        }
#pragma unroll
        for (int idx = tid; idx < BK * (BN / 8); idx += 256) {
            int r = idx / (BN / 8), q = idx % (BN / 8);
            size_t go = (size_t)(kbase + r) * N + q * 8;
            int so = r * BNP + q * 8;
            __pipeline_memcpy_async(bs_hi(s) + so, gw2_hi + go, 16);
            __pipeline_memcpy_async(bs_lo(s) + so, gw2_lo + go, 16);
        }
    };

    wmma::fragment<wmma::accumulator, 16, 16, 16, float> acc[AM][AN];
#pragma unroll
    for (int m = 0; m < AM; m++)
#pragma unroll
        for (int n = 0; n < AN; n++) wmma::fill_fragment(acc[m][n], 0.f);

    copy_stage(0, 0);
    __pipeline_commit();

    for (int t = 0; t < T; t++) {
        __pipeline_wait_prior(0);
        __syncthreads();
        if (t + 1 < T) {
            copy_stage((t + 1) & 1, t + 1);
            __pipeline_commit();
        }
        const int s = t & 1;
#pragma unroll
        for (int kk = 0; kk < KK; kk++) {
            wmma::fragment<wmma::matrix_a, 16, 16, 16, __nv_bfloat16, wmma::row_major> ahi[AM], alo[AM];
#pragma unroll
            for (int m = 0; m < AM; m++) {
                int o = (wm * 32 + m * 16) * BKP + kk * 16;
                wmma::load_matrix_sync(ahi[m], as_hi(s) + o, BKP);
                wmma::load_matrix_sync(alo[m], as_lo(s) + o, BKP);
            }
#pragma unroll
            for (int n = 0; n < AN; n++) {
                wmma::fragment<wmma::matrix_b, 16, 16, 16, __nv_bfloat16, wmma::row_major> bhi, blo;
                int o = (kk * 16) * BNP + wn * 32 + n * 16;
                wmma::load_matrix_sync(bhi, bs_hi(s) + o, BNP);
                wmma::load_matrix_sync(blo, bs_lo(s) + o, BNP);
#pragma unroll
                for (int m = 0; m < AM; m++) {
                    wmma::mma_sync(acc[m][n], alo[m], bhi, acc[m][n]);
                    wmma::mma_sync(acc[m][n], ahi[m], blo, acc[m][n]);
                    wmma::mma_sync(acc[m][n], ahi[m], bhi, acc[m][n]);
                }
            }
        }
    }

#pragma unroll
    for (int m = 0; m < AM; m++)
#pragma unroll
        for (int n = 0; n < AN; n++)
            wmma::store_matrix_sync(g_t + (size_t)(row0 + wm * 32 + m * 16) * N + wn * 32 + n * 16,
                                    acc[m][n], N, wmma::mem_row_major);
}

// ---------------------------------------------------------------------------
// Launch: fork-join. Chain A (main): wsplit + fused GEMM1.
// Chain B (s2): CSR build. Join before agg1.
// ---------------------------------------------------------------------------
extern "C" void kernel_launch(void* const* d_in, const int* in_sizes, int n_in,
                              void* d_out, int out_size) {
    const float* x   = (const float*)d_in[0];
    const int*   ei  = (const int*)d_in[1];
    const float* W1  = (const float*)d_in[2];
    const float* b1  = (const float*)d_in[3];
    const float* W2  = (const float*)d_in[4];
    const float* b2  = (const float*)d_in[5];
    float*       out = (float*)d_out;

    const int N = in_sizes[0] / IN_F;   // 50000
    const int E = in_sizes[1] / 2;      // 800000
    const int TB = 256;
    const int NB = (N + 255) / 256;

    constexpr int SM1 = 2 * 8192 + 2 * (64 * 48 * 2) + 2 * (2 * 32 * 136 * 2);  // 63488
    constexpr int SM2 = 2 * (2 * 128 * 48 * 2 + 2 * 32 * 80 * 2);               // 69632

    static cudaStream_t s2 = nullptr;
    static cudaEvent_t ev_fork = nullptr, ev_join = nullptr;
    if (s2 == nullptr) {
        cudaStreamCreateWithFlags(&s2, cudaStreamNonBlocking);
        cudaEventCreateWithFlags(&ev_fork, cudaEventDisableTiming);
        cudaEventCreateWithFlags(&ev_join, cudaEventDisableTiming);
        cudaFuncSetAttribute((const void*)gemm1_fused_kernel,
                             cudaFuncAttributeMaxDynamicSharedMemorySize, SM1);
        cudaFuncSetAttribute((const void*)gemm2_kernel,
                             cudaFuncAttributeMaxDynamicSharedMemorySize, SM2);
    }

    // Fork
    cudaEventRecord(ev_fork, 0);
    cudaStreamWaitEvent(s2, ev_fork, 0);

    // Chain B (s2): CSR build (g_cnt is all-zero by invariant)
    detect_kernel<<<1, 32, 0, s2>>>(ei);
    hist_kernel<<<(E + TB - 1) / TB, TB, 0, s2>>>(ei, E);
    scan_local_kernel<<<NB, 256, 0, s2>>>(N);
    scan_bsum_kernel<<<1, 256, 0, s2>>>(NB);
    scan_apply_kernel<<<NB, 256, 0, s2>>>(N);
    scatter_kernel<<<(E + TB - 1) / TB, TB, 0, s2>>>(ei, E);
    cudaEventRecord(ev_join, s2);

    // Chain A (main): weight split + fused GEMM1 (x split inside)
    wsplit_kernel<<<((IN_F * H_F + H_F * OUT_F) / 4 + TB - 1) / TB, TB>>>(W1, W2);
    gemm1_fused_kernel<<<NPAD / 64, 256, SM1>>>(x);

    // Join
    cudaStreamWaitEvent(0, ev_join, 0);

    agg1_kernel<<<(N + 7) / 8, 256>>>(b1, N);
    gemm2_kernel<<<NPAD / 128, 256, SM2>>>();
    agg2_kernel<<<(N + 15) / 16, 256>>>(b2, out, N);
}